// round 5
// baseline (speedup 1.0000x reference)
#include <cuda_runtime.h>

#define NB 32
#define NA 8400
#define NC 80
#define NM 64
#define KTOP 13
#define FEPS 1e-9f
#define CAP 2048
#define NBIN 64
#define HB 33                     /* hist blocks: ceil(8400/256) */
#define MAXPOS (NB * NM * KTOP)
#define APB (NA / 4)              /* 2100 anchor-quads per batch */

// Persistent scratch (device globals)
__device__ unsigned long long g_bits[NB * NA];
__device__ float              g_maxmet[NB * NM];
__device__ float              g_maxiou[NB * NM];
__device__ float2             g_apb[NA];
__device__ int                g_aidx[NA];
__device__ int                g_histpb[HB * NBIN];   // per-block hist (overwrite)
__device__ int                g_binstart[NBIN + 1];
__device__ int                g_poscnt;
__device__ int2               g_poslist[MAXPOS];

__device__ __forceinline__ float iou_fn(float gx1, float gy1, float gx2, float gy2,
                                        float garea, float4 p) {
    float ix1 = fmaxf(gx1, p.x), iy1 = fmaxf(gy1, p.y);
    float ix2 = fminf(gx2, p.z), iy2 = fminf(gy2, p.w);
    float ov  = fmaxf(ix2 - ix1, 0.f) * fmaxf(iy2 - iy1, 0.f);
    float pa  = fmaxf(p.z - p.x, 0.f) * fmaxf(p.w - p.y, 0.f);
    return ov / (garea + pa - ov + FEPS);
}

__device__ __forceinline__ int ybin(float y) {
    int b = (int)(y * (NBIN / 640.0f));
    return min(max(b, 0), NBIN - 1);
}

// ---------------------------------------------------------------------------
// Kernel 1: zero scratch + per-block anchor histogram (no cross-block deps)
// ---------------------------------------------------------------------------
__global__ __launch_bounds__(256)
void k_prep(const float* __restrict__ ap) {
    int blk = blockIdx.x, t = threadIdx.x;
    int gid = blk * 256 + t, gs = gridDim.x * 256;

    for (int i = gid; i < NB * NA; i += gs) g_bits[i] = 0ull;
    if (gid < NB * NM) { g_maxmet[gid] = 0.f; g_maxiou[gid] = 0.f; }
    if (gid == 0) g_poscnt = 0;

    if (blk < HB) {
        __shared__ int lh[NBIN];
        if (t < NBIN) lh[t] = 0;
        __syncthreads();
        int a = blk * 256 + t;
        if (a < NA) atomicAdd(&lh[ybin(((const float2*)ap)[a].y)], 1);
        __syncthreads();
        if (t < NBIN) g_histpb[blk * NBIN + t] = lh[t];
    }
}

// ---------------------------------------------------------------------------
// Kernel 2: scatter anchors into y-bin order; each block derives its offsets
// from g_histpb locally (no global atomics). Block 0 publishes g_binstart.
// ---------------------------------------------------------------------------
__global__ __launch_bounds__(256)
void k_scatter(const float* __restrict__ ap) {
    __shared__ int s_tot[NBIN], s_pre[NBIN], s_start[NBIN + 1], s_cnt[NBIN];
    int t = threadIdx.x, blk = blockIdx.x;

    if (t < NBIN) {
        int tot = 0, pre = 0;
        for (int b2 = 0; b2 < HB; b2++) {
            int h = g_histpb[b2 * NBIN + t];
            if (b2 < blk) pre += h;
            tot += h;
        }
        s_tot[t] = tot; s_pre[t] = pre; s_cnt[t] = 0;
    }
    __syncthreads();
    if (t == 0) {
        int acc = 0;
        for (int i = 0; i < NBIN; i++) { s_start[i] = acc; acc += s_tot[i]; }
        s_start[NBIN] = acc;
    }
    __syncthreads();

    int a = blk * 256 + t;
    if (a < NA) {
        float2 c = ((const float2*)ap)[a];
        int bin = ybin(c.y);
        int pos = s_start[bin] + s_pre[bin] + atomicAdd(&s_cnt[bin], 1);
        g_apb[pos]  = c;
        g_aidx[pos] = a;
    }
    if (blk == 0 && t <= NBIN) g_binstart[t] = s_start[t];
}

// ---------------------------------------------------------------------------
// Kernel 3: per (b,m) — scan y-bin window, compact candidates as unique packed
// keys (value desc, index asc == lax.top_k order), select top-13, scatter bits
// ---------------------------------------------------------------------------
__global__ __launch_bounds__(256)
void k_topk(const float* __restrict__ ps,
            const float* __restrict__ pb,
            const int*   __restrict__ gl,
            const float* __restrict__ gb,
            const float* __restrict__ pm)
{
    int bm = blockIdx.x;
    if (pm[bm] == 0.f) return;
    int b = bm >> 6, m = bm & 63;

    __shared__ unsigned long long keys[CAP];
    __shared__ unsigned long long wred[8];
    __shared__ unsigned long long s_kprev;
    __shared__ int s_cnt;

    int t = threadIdx.x, lane = t & 31;
    if (t == 0) s_cnt = 0;
    __syncthreads();

    float gx1 = gb[bm * 4 + 0], gy1 = gb[bm * 4 + 1];
    float gx2 = gb[bm * 4 + 2], gy2 = gb[bm * 4 + 3];
    float garea = fmaxf(gx2 - gx1, 0.f) * fmaxf(gy2 - gy1, 0.f);
    int lab = gl[bm];

    const float4* pbv = (const float4*)pb + (size_t)b * NA;
    const float*  psb = ps + (size_t)b * NA * NC + lab;

    int lo = g_binstart[ybin(gy1)];
    int hi = g_binstart[ybin(gy2) + 1];

    for (int base = lo; base < hi; base += 256) {
        int i = base + t;
        bool inb = i < hi;
        float d = -1.f;
        int a = 0;
        if (inb) {
            float2 c = g_apb[i];
            a = g_aidx[i];
            d = fminf(fminf(c.x - gx1, c.y - gy1), fminf(gx2 - c.x, gy2 - c.y));
        }
        bool pred = inb && (d > FEPS);
        unsigned act = __ballot_sync(0xffffffffu, pred);
        if (pred) {
            float4 p   = pbv[a];
            float  iou = iou_fn(gx1, gy1, gx2, gy2, garea, p);
            float  cls = __ldg(psb + (size_t)a * NC);
            float  i2  = iou * iou;
            float  met = cls * (i2 * i2 * i2);
            unsigned long long key =
                ((unsigned long long)__float_as_uint(met) << 32) | (unsigned)(NA - a);
            int rank   = __popc(act & ((1u << lane) - 1u));
            int leader = __ffs(act) - 1;
            int pos;
            if (lane == leader) pos = atomicAdd(&s_cnt, __popc(act));
            pos = __shfl_sync(act, pos, leader) + rank;
            if (pos < CAP) keys[pos] = key;
        }
    }
    __syncthreads();
    int n = min(s_cnt, CAP);

    unsigned long long kprev = 0xFFFFFFFFFFFFFFFFull;
    for (int k = 0; k < KTOP; k++) {
        unsigned long long best = 0ull;
        for (int i = t; i < n; i += 256) {
            unsigned long long kk = keys[i];
            if (kk < kprev && kk > best) best = kk;
        }
        #pragma unroll
        for (int s = 16; s; s >>= 1) {
            unsigned long long o = __shfl_down_sync(0xffffffffu, best, s);
            if (o > best) best = o;
        }
        if (lane == 0) wred[t >> 5] = best;
        __syncthreads();
        if (t < 32) {
            unsigned long long b2 = (t < 8) ? wred[t] : 0ull;
            #pragma unroll
            for (int s = 4; s; s >>= 1) {
                unsigned long long o = __shfl_down_sync(0xffffffffu, b2, s);
                if (o > b2) b2 = o;
            }
            if (t == 0) {
                s_kprev = b2;
                if (b2) {
                    int aidx = NA - (int)(b2 & 0xffffffffu);
                    atomicOr(&g_bits[(size_t)b * NA + aidx], 1ull << m);
                }
            }
        }
        __syncthreads();
        kprev = s_kprev;
        if (!kprev) break;
    }
}

// ---------------------------------------------------------------------------
// Kernel 4: 4 anchors/thread — resolve multi-assignment, emit labels/bboxes,
// per-(b,m) maxima, warp-aggregated positive-list append. No barriers.
// ---------------------------------------------------------------------------
__global__ __launch_bounds__(256)
void k_assign(const float* __restrict__ ps,
              const float* __restrict__ pb,
              const int*   __restrict__ gl,
              const float* __restrict__ gb,
              const int*   __restrict__ bgp,
              float* __restrict__ out_lab,   // [B,A]
              float* __restrict__ out_box)   // [B,A,4]
{
    int tid  = blockIdx.x * 256 + threadIdx.x;
    int lane = threadIdx.x & 31;
    bool live = tid < NB * APB;

    unsigned long long bits[4] = {0ull, 0ull, 0ull, 0ull};
    size_t base = 0;
    int b = 0;
    if (live) {
        b = tid / APB;
        int a0 = (tid - b * APB) * 4;
        base = (size_t)b * NA + a0;
        ulonglong2 w0 = *(const ulonglong2*)&g_bits[base];
        ulonglong2 w1 = *(const ulonglong2*)&g_bits[base + 2];
        bits[0] = w0.x; bits[1] = w0.y; bits[2] = w1.x; bits[3] = w1.y;
    }

    const float4* gbv = (const float4*)gb + b * NM;
    float4 bgbox = live ? __ldg(gbv) : make_float4(0.f, 0.f, 0.f, 0.f);
    float  bgl   = live ? (float)*bgp : 0.f;

    int   mfin[4];
    float lab4[4];
    float4 box4[4];
    int cnt = 0;

    #pragma unroll
    for (int j = 0; j < 4; j++) {
        mfin[j] = -1; lab4[j] = bgl; box4[j] = bgbox;
        if (!bits[j]) continue;
        int m;
        if (__popcll(bits[j]) > 1) {
            float4 p = __ldg((const float4*)pb + base + j);
            float bestv = -1.f; int bestm = 0;
            for (int mm = 0; mm < NM; mm++) {
                float4 g = __ldg(gbv + mm);
                float ga = fmaxf(g.z - g.x, 0.f) * fmaxf(g.w - g.y, 0.f);
                float iou = iou_fn(g.x, g.y, g.z, g.w, ga, p);
                if (iou > bestv) { bestv = iou; bestm = mm; }
            }
            m = bestm;
        } else {
            m = __ffsll((long long)bits[j]) - 1;
        }
        mfin[j] = m;
        int lab = __ldg(&gl[b * NM + m]);
        lab4[j] = (float)lab;
        float4 g = __ldg(gbv + m);
        box4[j] = g;
        float4 p = __ldg((const float4*)pb + base + j);
        float ga = fmaxf(g.z - g.x, 0.f) * fmaxf(g.w - g.y, 0.f);
        float iou = iou_fn(g.x, g.y, g.z, g.w, ga, p);
        float cls = __ldg(&ps[(base + j) * NC + lab]);
        float i2 = iou * iou;
        float align = cls * (i2 * i2 * i2);
        atomicMax((int*)&g_maxmet[b * NM + m], __float_as_int(align));
        atomicMax((int*)&g_maxiou[b * NM + m], __float_as_int(iou));
        cnt++;
    }

    if (live) {
        *(float4*)&out_lab[base] = make_float4(lab4[0], lab4[1], lab4[2], lab4[3]);
        float4* ob = (float4*)out_box + base;
        ob[0] = box4[0]; ob[1] = box4[1]; ob[2] = box4[2]; ob[3] = box4[3];
    }

    int pre = cnt;
    #pragma unroll
    for (int s = 1; s < 32; s <<= 1) {
        int o = __shfl_up_sync(0xffffffffu, pre, s);
        if (lane >= s) pre += o;
    }
    int total = __shfl_sync(0xffffffffu, pre, 31);
    int ex = pre - cnt;
    int gbase = 0;
    if (lane == 31 && total) gbase = atomicAdd(&g_poscnt, total);
    gbase = __shfl_sync(0xffffffffu, gbase, 31);
    if (cnt) {
        int w = 0;
        #pragma unroll
        for (int j = 0; j < 4; j++)
            if (mfin[j] >= 0) g_poslist[gbase + ex + (w++)] = make_int2((int)(base + j), mfin[j]);
    }
}

// ---------------------------------------------------------------------------
// Kernel 5: over compact positive list — normalized score scatter
// ---------------------------------------------------------------------------
__global__ __launch_bounds__(256)
void k_scores(const float* __restrict__ ps,
              const float* __restrict__ pb,
              const int*   __restrict__ gl,
              const float* __restrict__ gb,
              const int*   __restrict__ bgp,
              float* __restrict__ out_sc)    // [B,A,C]
{
    int tid = blockIdx.x * 256 + threadIdx.x;
    if (tid >= g_poscnt) return;
    int2 e = g_poslist[tid];
    size_t ia = (size_t)(unsigned)e.x;
    int m = e.y;
    int b = (int)(ia / NA);
    int bmi = b * NM + m;

    float4 p = __ldg((const float4*)pb + ia);
    float4 g = __ldg((const float4*)gb + bmi);
    float ga = fmaxf(g.z - g.x, 0.f) * fmaxf(g.w - g.y, 0.f);
    float iou = iou_fn(g.x, g.y, g.z, g.w, ga, p);
    int lab = __ldg(&gl[bmi]);
    float cls = __ldg(&ps[ia * NC + lab]);
    float i2 = iou * iou;
    float align = cls * (i2 * i2 * i2);
    float factor = align / (g_maxmet[bmi] + FEPS) * g_maxiou[bmi];

    int bg = *bgp;
    int col = (lab < bg) ? lab : (lab - 1);
    out_sc[ia * NC + col] = factor;
}

// ---------------------------------------------------------------------------
extern "C" void kernel_launch(void* const* d_in, const int* in_sizes, int n_in,
                              void* d_out, int out_size) {
    const float* ps  = (const float*)d_in[0];
    const float* pb  = (const float*)d_in[1];
    const float* ap  = (const float*)d_in[2];
    const int*   gl  = (const int*)  d_in[3];
    const float* gb  = (const float*)d_in[4];
    const float* pm  = (const float*)d_in[5];
    const int*   bgp = (const int*)  d_in[6];

    float* out      = (float*)d_out;
    float* out_lab  = out;
    float* out_box  = out + (size_t)NB * NA;
    float* out_sc   = out + (size_t)NB * NA * 5;

    static cudaStream_t s2 = nullptr;
    static cudaEvent_t ev_fork = nullptr, ev_join = nullptr;
    if (!s2) {
        cudaStreamCreateWithFlags(&s2, cudaStreamNonBlocking);
        cudaEventCreateWithFlags(&ev_fork, cudaEventDisableTiming);
        cudaEventCreateWithFlags(&ev_join, cudaEventDisableTiming);
    }

    // Fork: 86 MB memset of the scores region overlaps the whole compute chain
    cudaEventRecord(ev_fork, 0);
    cudaStreamWaitEvent(s2, ev_fork, 0);
    cudaMemsetAsync(out_sc, 0, (size_t)NB * NA * NC * sizeof(float), s2);
    cudaEventRecord(ev_join, s2);

    k_prep<<<132, 256>>>(ap);
    k_scatter<<<HB, 256>>>(ap);
    k_topk<<<NB * NM, 256>>>(ps, pb, gl, gb, pm);
    k_assign<<<(NB * APB + 255) / 256, 256>>>(ps, pb, gl, gb, bgp, out_lab, out_box);

    cudaStreamWaitEvent(0, ev_join, 0);
    k_scores<<<(MAXPOS + 255) / 256, 256>>>(ps, pb, gl, gb, bgp, out_sc);
}

// round 6
// speedup vs baseline: 1.3108x; 1.3108x over previous
#include <cuda_runtime.h>

#define NB 32
#define NA 8400
#define NC 80
#define NM 64
#define KTOP 13
#define FEPS 1e-9f
#define CAP 2048
#define NBIN 64
#define HB 33                     /* ceil(8400/256) */
#define MAXPOS (NB * NM * KTOP)

// Persistent scratch (device globals)
__device__ unsigned long long g_bits[NB * NA];
__device__ float              g_maxmet[NB * NM];
__device__ float              g_maxiou[NB * NM];
__device__ float2             g_apb[NA];
__device__ int                g_aidx[NA];
__device__ int                g_histpb[HB * NBIN];
__device__ int                g_binstart[NBIN + 1];
__device__ int                g_candcnt;
__device__ int2               g_cand[MAXPOS];      // (global anchor idx, m) topk picks
__device__ int                g_poscnt;
__device__ int2               g_poslist[MAXPOS];   // resolved positives

__device__ __forceinline__ float iou_fn(float gx1, float gy1, float gx2, float gy2,
                                        float garea, float4 p) {
    float ix1 = fmaxf(gx1, p.x), iy1 = fmaxf(gy1, p.y);
    float ix2 = fminf(gx2, p.z), iy2 = fminf(gy2, p.w);
    float ov  = fmaxf(ix2 - ix1, 0.f) * fmaxf(iy2 - iy1, 0.f);
    float pa  = fmaxf(p.z - p.x, 0.f) * fmaxf(p.w - p.y, 0.f);
    return ov / (garea + pa - ov + FEPS);
}

__device__ __forceinline__ int ybin(float y) {
    int b = (int)(y * (NBIN / 640.0f));
    return min(max(b, 0), NBIN - 1);
}

// ---------------------------------------------------------------------------
// Kernel: zero scratch + per-block anchor histogram (no cross-block deps)
// ---------------------------------------------------------------------------
__global__ __launch_bounds__(256)
void k_prep(const float* __restrict__ ap) {
    int blk = blockIdx.x, t = threadIdx.x;
    int gid = blk * 256 + t, gs = gridDim.x * 256;

    ulonglong2 z2 = {0ull, 0ull};
    for (int i = gid; i < NB * NA / 2; i += gs) ((ulonglong2*)g_bits)[i] = z2;
    if (gid < NB * NM) { g_maxmet[gid] = 0.f; g_maxiou[gid] = 0.f; }
    if (gid == 0) { g_candcnt = 0; g_poscnt = 0; }

    if (blk < HB) {
        __shared__ int lh[NBIN];
        if (t < NBIN) lh[t] = 0;
        __syncthreads();
        int a = blk * 256 + t;
        if (a < NA) atomicAdd(&lh[ybin(((const float2*)ap)[a].y)], 1);
        __syncthreads();
        if (t < NBIN) g_histpb[blk * NBIN + t] = lh[t];
    }
}

// ---------------------------------------------------------------------------
// Kernel: scatter anchors into y-bin order; offsets derived locally.
// ---------------------------------------------------------------------------
__global__ __launch_bounds__(256)
void k_scatter(const float* __restrict__ ap) {
    __shared__ int s_tot[NBIN], s_pre[NBIN], s_start[NBIN + 1], s_cnt[NBIN];
    int t = threadIdx.x, blk = blockIdx.x;

    if (t < NBIN) {
        int tot = 0, pre = 0;
        for (int b2 = 0; b2 < HB; b2++) {
            int h = g_histpb[b2 * NBIN + t];
            if (b2 < blk) pre += h;
            tot += h;
        }
        s_tot[t] = tot; s_pre[t] = pre; s_cnt[t] = 0;
    }
    __syncthreads();
    if (t == 0) {
        int acc = 0;
        for (int i = 0; i < NBIN; i++) { s_start[i] = acc; acc += s_tot[i]; }
        s_start[NBIN] = acc;
    }
    __syncthreads();

    int a = blk * 256 + t;
    if (a < NA) {
        float2 c = ((const float2*)ap)[a];
        int bin = ybin(c.y);
        int pos = s_start[bin] + s_pre[bin] + atomicAdd(&s_cnt[bin], 1);
        g_apb[pos]  = c;
        g_aidx[pos] = a;
    }
    if (blk == 0 && t <= NBIN) g_binstart[t] = s_start[t];
}

// ---------------------------------------------------------------------------
// Kernel (side stream): broadcast background labels + gt-row-0 boxes to ALL
// anchors. Pure coalesced writes; positives overwritten later by k_fix.
// ---------------------------------------------------------------------------
__global__ __launch_bounds__(256)
void k_fill(const float* __restrict__ gb,
            const int*   __restrict__ bgp,
            float* __restrict__ out_lab,   // [B,A]
            float* __restrict__ out_box)   // [B,A,4]
{
    int tid = blockIdx.x * 256 + threadIdx.x;
    if (tid >= NB * NA / 4) return;
    int b = tid / (NA / 4);
    size_t base = (size_t)tid * 4;

    float bg = (float)*bgp;
    float4 g0 = __ldg((const float4*)gb + b * NM);

    *(float4*)&out_lab[base] = make_float4(bg, bg, bg, bg);
    float4* ob = (float4*)out_box + base;
    ob[0] = g0; ob[1] = g0; ob[2] = g0; ob[3] = g0;
}

// ---------------------------------------------------------------------------
// Kernel: per (b,m) — scan y-bin window, compact candidates as unique packed
// keys (value desc, index asc == lax.top_k order), select top-13, scatter
// bits + append picks to the global candidate list (one atomic per block).
// ---------------------------------------------------------------------------
__global__ __launch_bounds__(256)
void k_topk(const float* __restrict__ ps,
            const float* __restrict__ pb,
            const int*   __restrict__ gl,
            const float* __restrict__ gb,
            const float* __restrict__ pm)
{
    int bm = blockIdx.x;
    if (pm[bm] == 0.f) return;
    int b = bm >> 6, m = bm & 63;

    __shared__ unsigned long long keys[CAP];
    __shared__ unsigned long long wred[8];
    __shared__ unsigned long long s_kprev;
    __shared__ int s_cnt;
    __shared__ int s_picks[KTOP];

    int t = threadIdx.x, lane = t & 31;
    if (t == 0) s_cnt = 0;
    __syncthreads();

    float gx1 = gb[bm * 4 + 0], gy1 = gb[bm * 4 + 1];
    float gx2 = gb[bm * 4 + 2], gy2 = gb[bm * 4 + 3];
    float garea = fmaxf(gx2 - gx1, 0.f) * fmaxf(gy2 - gy1, 0.f);
    int lab = gl[bm];

    const float4* pbv = (const float4*)pb + (size_t)b * NA;
    const float*  psb = ps + (size_t)b * NA * NC + lab;

    int lo = g_binstart[ybin(gy1)];
    int hi = g_binstart[ybin(gy2) + 1];

    for (int base = lo; base < hi; base += 256) {
        int i = base + t;
        bool inb = i < hi;
        float d = -1.f;
        int a = 0;
        if (inb) {
            float2 c = g_apb[i];
            a = g_aidx[i];
            d = fminf(fminf(c.x - gx1, c.y - gy1), fminf(gx2 - c.x, gy2 - c.y));
        }
        bool pred = inb && (d > FEPS);
        unsigned act = __ballot_sync(0xffffffffu, pred);
        if (pred) {
            float4 p   = pbv[a];
            float  iou = iou_fn(gx1, gy1, gx2, gy2, garea, p);
            float  cls = __ldg(psb + (size_t)a * NC);
            float  i2  = iou * iou;
            float  met = cls * (i2 * i2 * i2);
            unsigned long long key =
                ((unsigned long long)__float_as_uint(met) << 32) | (unsigned)(NA - a);
            int rank   = __popc(act & ((1u << lane) - 1u));
            int leader = __ffs(act) - 1;
            int pos;
            if (lane == leader) pos = atomicAdd(&s_cnt, __popc(act));
            pos = __shfl_sync(act, pos, leader) + rank;
            if (pos < CAP) keys[pos] = key;
        }
    }
    __syncthreads();
    int n = min(s_cnt, CAP);

    int npick = 0;
    unsigned long long kprev = 0xFFFFFFFFFFFFFFFFull;
    for (int k = 0; k < KTOP; k++) {
        unsigned long long best = 0ull;
        for (int i = t; i < n; i += 256) {
            unsigned long long kk = keys[i];
            if (kk < kprev && kk > best) best = kk;
        }
        #pragma unroll
        for (int s = 16; s; s >>= 1) {
            unsigned long long o = __shfl_down_sync(0xffffffffu, best, s);
            if (o > best) best = o;
        }
        if (lane == 0) wred[t >> 5] = best;
        __syncthreads();
        if (t < 32) {
            unsigned long long b2 = (t < 8) ? wred[t] : 0ull;
            #pragma unroll
            for (int s = 4; s; s >>= 1) {
                unsigned long long o = __shfl_down_sync(0xffffffffu, b2, s);
                if (o > b2) b2 = o;
            }
            if (t == 0) {
                s_kprev = b2;
                if (b2) {
                    int aidx = NA - (int)(b2 & 0xffffffffu);
                    s_picks[k] = aidx;
                    atomicOr(&g_bits[(size_t)b * NA + aidx], 1ull << m);
                }
            }
        }
        __syncthreads();
        kprev = s_kprev;
        if (!kprev) break;
        npick = k + 1;
    }

    if (t == 0 && npick) {
        int base = atomicAdd(&g_candcnt, npick);
        for (int k = 0; k < npick; k++)
            g_cand[base + k] = make_int2(b * NA + s_picks[k], m);
    }
}

// ---------------------------------------------------------------------------
// Kernel: sparse resolution over the candidate list (≤26.6K entries).
// Representative entry per anchor = entry whose m is the anchor's lowest set
// bit. Resolves multi-assignment, scatters label/box, accumulates maxima,
// appends resolved positives.
// ---------------------------------------------------------------------------
__global__ __launch_bounds__(256)
void k_fix(const float* __restrict__ ps,
           const float* __restrict__ pb,
           const int*   __restrict__ gl,
           const float* __restrict__ gb,
           float* __restrict__ out_lab,
           float* __restrict__ out_box)
{
    int tid = blockIdx.x * 256 + threadIdx.x;
    int lane = threadIdx.x & 31;
    bool rep = false;
    size_t ia = 0;
    int mfin = 0, b = 0;

    if (tid < g_candcnt) {
        int2 e = g_cand[tid];
        ia = (size_t)(unsigned)e.x;
        unsigned long long bits = g_bits[ia];
        int first = __ffsll((long long)bits) - 1;
        if (e.y == first) {                 // representative for this anchor
            rep = true;
            b = (int)(ia / NA);
            mfin = first;
            if (__popcll(bits) > 1) {
                const float4* gbv = (const float4*)gb + b * NM;
                float4 p = __ldg((const float4*)pb + ia);
                float bestv = -1.f; int bestm = 0;
                for (int mm = 0; mm < NM; mm++) {
                    float4 g = __ldg(gbv + mm);
                    float ga = fmaxf(g.z - g.x, 0.f) * fmaxf(g.w - g.y, 0.f);
                    float iou = iou_fn(g.x, g.y, g.z, g.w, ga, p);
                    if (iou > bestv) { bestv = iou; bestm = mm; }
                }
                mfin = bestm;
            }
            int bmi = b * NM + mfin;
            int lab = __ldg(&gl[bmi]);
            float4 g = __ldg((const float4*)gb + bmi);
            out_lab[ia] = (float)lab;
            ((float4*)out_box)[ia] = g;

            float4 p = __ldg((const float4*)pb + ia);
            float ga = fmaxf(g.z - g.x, 0.f) * fmaxf(g.w - g.y, 0.f);
            float iou = iou_fn(g.x, g.y, g.z, g.w, ga, p);
            float cls = __ldg(&ps[ia * NC + lab]);
            float i2 = iou * iou;
            float align = cls * (i2 * i2 * i2);
            atomicMax((int*)&g_maxmet[bmi], __float_as_int(align));
            atomicMax((int*)&g_maxiou[bmi], __float_as_int(iou));
        }
    }

    // warp-aggregated append of resolved positives
    unsigned act = __ballot_sync(0xffffffffu, rep);
    if (rep) {
        int rank = __popc(act & ((1u << lane) - 1u));
        int leader = __ffs(act) - 1;
        int base;
        if (lane == leader) base = atomicAdd(&g_poscnt, __popc(act));
        base = __shfl_sync(act, base, leader) + rank;
        g_poslist[base] = make_int2((int)ia, mfin);
    }
}

// ---------------------------------------------------------------------------
// Kernel: over resolved positives — normalized score scatter
// ---------------------------------------------------------------------------
__global__ __launch_bounds__(256)
void k_scores(const float* __restrict__ ps,
              const float* __restrict__ pb,
              const int*   __restrict__ gl,
              const float* __restrict__ gb,
              const int*   __restrict__ bgp,
              float* __restrict__ out_sc)    // [B,A,C]
{
    int tid = blockIdx.x * 256 + threadIdx.x;
    if (tid >= g_poscnt) return;
    int2 e = g_poslist[tid];
    size_t ia = (size_t)(unsigned)e.x;
    int m = e.y;
    int b = (int)(ia / NA);
    int bmi = b * NM + m;

    float4 p = __ldg((const float4*)pb + ia);
    float4 g = __ldg((const float4*)gb + bmi);
    float ga = fmaxf(g.z - g.x, 0.f) * fmaxf(g.w - g.y, 0.f);
    float iou = iou_fn(g.x, g.y, g.z, g.w, ga, p);
    int lab = __ldg(&gl[bmi]);
    float cls = __ldg(&ps[ia * NC + lab]);
    float i2 = iou * iou;
    float align = cls * (i2 * i2 * i2);
    float factor = align / (g_maxmet[bmi] + FEPS) * g_maxiou[bmi];

    int bg = *bgp;
    int col = (lab < bg) ? lab : (lab - 1);
    out_sc[ia * NC + col] = factor;
}

// ---------------------------------------------------------------------------
extern "C" void kernel_launch(void* const* d_in, const int* in_sizes, int n_in,
                              void* d_out, int out_size) {
    const float* ps  = (const float*)d_in[0];
    const float* pb  = (const float*)d_in[1];
    const float* ap  = (const float*)d_in[2];
    const int*   gl  = (const int*)  d_in[3];
    const float* gb  = (const float*)d_in[4];
    const float* pm  = (const float*)d_in[5];
    const int*   bgp = (const int*)  d_in[6];

    float* out      = (float*)d_out;
    float* out_lab  = out;
    float* out_box  = out + (size_t)NB * NA;
    float* out_sc   = out + (size_t)NB * NA * 5;

    static cudaStream_t s2 = nullptr;
    static cudaEvent_t ev_fork = nullptr, ev_join = nullptr;
    if (!s2) {
        cudaStreamCreateWithFlags(&s2, cudaStreamNonBlocking);
        cudaEventCreateWithFlags(&ev_fork, cudaEventDisableTiming);
        cudaEventCreateWithFlags(&ev_join, cudaEventDisableTiming);
    }

    // Side stream: 86 MB memset + dense background fill, concurrent with the
    // binning/topk chain. Joined before k_fix overwrites positives.
    cudaEventRecord(ev_fork, 0);
    cudaStreamWaitEvent(s2, ev_fork, 0);
    cudaMemsetAsync(out_sc, 0, (size_t)NB * NA * NC * sizeof(float), s2);
    k_fill<<<(NB * NA / 4 + 255) / 256, 256, 0, s2>>>(gb, bgp, out_lab, out_box);
    cudaEventRecord(ev_join, s2);

    k_prep<<<132, 256>>>(ap);
    k_scatter<<<HB, 256>>>(ap);
    k_topk<<<NB * NM, 256>>>(ps, pb, gl, gb, pm);

    cudaStreamWaitEvent(0, ev_join, 0);
    k_fix<<<(MAXPOS + 255) / 256, 256>>>(ps, pb, gl, gb, out_lab, out_box);
    k_scores<<<(MAXPOS + 255) / 256, 256>>>(ps, pb, gl, gb, bgp, out_sc);
}